// round 13
// baseline (speedup 1.0000x reference)
#include <cuda_runtime.h>
#include <cuda_fp16.h>
#include <cstdint>
#include <cstddef>

#define NN 50000
#define EE 800000
#define FF 256
#define LL 3
#define NB 196   // ceil(NN/256)

// ---------------- scratch (device globals) ----------------
__device__ float g_deg[NN];
__device__ float g_dinv[NN];
__device__ int   g_cnt[NN];
__device__ int   g_rowptr[NN + 1];
__device__ int   g_cursor[NN];
__device__ int   g_bsum[NB];
__device__ int   g_boff[NB];
__device__ int   g_csrc[EE];
__device__ float g_cw[EE];
__device__ __half g_h[(size_t)NN * FF];      // h = x@Wi in fp16 (agg gather operand)
__device__ float  g_y[(size_t)NN * FF];      // y = x@Wr + b in fp32
__device__ __half g_xf16[(size_t)NN * FF];   // activations in fp16 (GEMM A operand)
// fused transposed weights, fp16 2-term split: [layer][512][256]
// rows 0-255 = Wi^T, rows 256-511 = Wr^T
__device__ __half g_Whi[3 * 512 * 256];
__device__ __half g_Wlo[3 * 512 * 256];

// ---------------- helpers ----------------
__device__ __forceinline__ uint32_t smem_u32(const void* p) {
    uint32_t a;
    asm("{ .reg .u64 t; cvta.to.shared.u64 t, %1; cvt.u32.u64 %0, t; }"
        : "=r"(a) : "l"(p));
    return a;
}
// 128B-row swizzle (SW128)
__device__ __forceinline__ uint32_t swz(uint32_t off) { return off ^ ((off >> 3) & 0x70); }

__device__ __forceinline__ void ldmx4(uint32_t* r, uint32_t addr) {
    asm volatile("ldmatrix.sync.aligned.m8n8.x4.shared.b16 {%0,%1,%2,%3}, [%4];"
                 : "=r"(r[0]), "=r"(r[1]), "=r"(r[2]), "=r"(r[3]) : "r"(addr));
}
__device__ __forceinline__ void mma16816(float* c, const uint32_t* a, const uint32_t* b) {
    asm volatile(
        "mma.sync.aligned.m16n8k16.row.col.f32.f16.f16.f32 "
        "{%0,%1,%2,%3}, {%4,%5,%6,%7}, {%8,%9}, {%0,%1,%2,%3};"
        : "+f"(c[0]), "+f"(c[1]), "+f"(c[2]), "+f"(c[3])
        : "r"(a[0]), "r"(a[1]), "r"(a[2]), "r"(a[3]), "r"(b[0]), "r"(b[1]));
}
__device__ __forceinline__ void cp16(uint32_t dst, const void* src, uint32_t valid) {
    asm volatile("cp.async.cg.shared.global [%0], [%1], 16, %2;"
                 :: "r"(dst), "l"(src), "r"(valid ? 16u : 0u));
}
#define CP_COMMIT() asm volatile("cp.async.commit_group;" ::: "memory")
template <int N> __device__ __forceinline__ void cp_wait() {
    asm volatile("cp.async.wait_group %0;" :: "n"(N) : "memory");
}

// ---------------- setup kernels ----------------
__global__ void hist_kernel(const int* __restrict__ src, const int* __restrict__ dst,
                            const float* __restrict__ w) {
    int e = blockIdx.x * blockDim.x + threadIdx.x;
    if (e >= EE) return;
    int d = dst[e];
    atomicAdd(&g_deg[d], w[e]);
    atomicAdd(&g_cnt[d], 1);
}

__global__ void dinv_kernel() {
    int n = blockIdx.x * blockDim.x + threadIdx.x;
    if (n >= NN) return;
    float d = g_deg[n];
    g_dinv[n] = (d > 0.f) ? rsqrtf(d) : 0.f;
}

__global__ void scan_local() {
    __shared__ int sh[256];
    int b = blockIdx.x, tid = threadIdx.x, i = b * 256 + tid;
    int v = (i < NN) ? g_cnt[i] : 0;
    sh[tid] = v;
    __syncthreads();
    #pragma unroll
    for (int off = 1; off < 256; off <<= 1) {
        int t2 = (tid >= off) ? sh[tid - off] : 0;
        __syncthreads();
        sh[tid] += t2;
        __syncthreads();
    }
    if (i < NN) g_rowptr[i] = sh[tid];
    if (tid == 255) g_bsum[b] = sh[255];
}
__global__ void scan_blocks() {
    __shared__ int sh[256];
    int tid = threadIdx.x;
    int v = (tid < NB) ? g_bsum[tid] : 0;
    sh[tid] = v;
    __syncthreads();
    #pragma unroll
    for (int off = 1; off < 256; off <<= 1) {
        int t2 = (tid >= off) ? sh[tid - off] : 0;
        __syncthreads();
        sh[tid] += t2;
        __syncthreads();
    }
    if (tid < NB) g_boff[tid] = sh[tid] - v;
    if (tid == NB - 1) g_rowptr[NN] = sh[tid];
}
__global__ void scan_finish() {
    int i = blockIdx.x * 256 + threadIdx.x;
    if (i >= NN) return;
    int excl = g_rowptr[i] - g_cnt[i] + g_boff[blockIdx.x];
    g_rowptr[i] = excl;
    g_cursor[i] = excl;
}

__global__ void fill_kernel(const int* __restrict__ src, const int* __restrict__ dst,
                            const float* __restrict__ w) {
    int e = blockIdx.x * blockDim.x + threadIdx.x;
    if (e >= EE) return;
    int s = src[e];
    int d = dst[e];
    int pos = atomicAdd(&g_cursor[d], 1);
    g_csrc[pos] = s;
    g_cw[pos] = g_dinv[s] * w[e] * g_dinv[d];
}

// weights: transpose + fp16 2-term split into fused [l][512][256]
__global__ void convert_w_kernel(const float* __restrict__ Wi, const float* __restrict__ Wr) {
    int idx = blockIdx.x * blockDim.x + threadIdx.x;
    if (idx >= 3 * 512 * 256) return;
    int l = idx >> 17;
    int n = (idx >> 8) & 511;
    int k = idx & 255;
    const float* W = (n < 256) ? Wi : Wr;
    int nn = n & 255;
    float v = W[(size_t)l * FF * FF + (size_t)k * FF + nn];
    __half hi = __float2half(v);
    __half lo = __float2half(v - __half2float(hi));
    g_Whi[idx] = hi;
    g_Wlo[idx] = lo;
}

// layer-0 activations -> fp16
__global__ void convert_x_kernel(const float* __restrict__ x) {
    int idx = blockIdx.x * blockDim.x + threadIdx.x;   // over NN*FF/4
    if (idx >= NN * FF / 4) return;
    float4 v = *(const float4*)(x + idx * 4);
    uint2 p;
    *(__half2*)&p.x = __floats2half2_rn(v.x, v.y);
    *(__half2*)&p.y = __floats2half2_rn(v.z, v.w);
    *(uint2*)(g_xf16 + (size_t)idx * 4) = p;
}

// ---------------- HMMA fp16 GEMM (cp.async 2-stage, K-chunk 64) ----------------
// TERMS=1: H(fp16) = A @ Wi^T (hi only); W rows [0,256). grid.x=2
// TERMS=2: Y(fp32)+bias = A @ Wr^T (hi+lo); W rows [256,512). grid.x=2, ntBase=2
// CTA tile 128x128. SMEM rows 128B (64 fp16), SW128 swizzle.
// Stage: A 16KB + Wh 16KB (+ Wl 16KB for TERMS=2).
#define GSM1 65536
#define GSM2 98304
template <int TERMS>
__global__ __launch_bounds__(256, 2)
void hmma_gemm_kernel(const __half* __restrict__ A,
                      const __half* __restrict__ Whi,
                      const __half* __restrict__ Wlo,
                      const float* __restrict__ bias,
                      __half* __restrict__ H, float* __restrict__ Y,
                      int M, int ntBase) {
    constexpr uint32_t STAGE = (TERMS == 2) ? 49152u : 32768u;
    extern __shared__ __align__(1024) uint8_t dsm[];
    const uint32_t base = smem_u32(dsm);

    int t = threadIdx.x;
    int lane = t & 31, wid = t >> 5;
    int wm = wid >> 2;        // 0..1
    int wn = wid & 3;         // 0..3
    int row0 = blockIdx.y * 128;
    int nt   = ntBase + blockIdx.x;
    int n0   = nt * 128;      // fused W row base

    float acc[4][4][4];
    #pragma unroll
    for (int i = 0; i < 4; i++)
        #pragma unroll
        for (int j = 0; j < 4; j++)
            #pragma unroll
            for (int q = 0; q < 4; q++) acc[i][j][q] = 0.f;

    auto load_chunk = [&](int c, int stage) {
        int k0 = c * 64;
        uint32_t sA  = base + (uint32_t)stage * STAGE;
        uint32_t sWh = sA + 16384u;
        uint32_t sWl = sA + 32768u;
        #pragma unroll
        for (int u = 0; u < 4; u++) {
            int idx = t + u * 256;            // 0..1023 = 128 rows x 8 segs
            int r = idx >> 3;
            int seg = idx & 7;
            uint32_t soff = swz((uint32_t)r * 128 + (uint32_t)seg * 16);
            int gm = row0 + r;
            const __half* pa = A + (size_t)(gm < M ? gm : 0) * FF + k0 + seg * 8;
            cp16(sA + soff, pa, (uint32_t)(gm < M));
            const __half* ph = Whi + (size_t)(n0 + r) * FF + k0 + seg * 8;
            cp16(sWh + soff, ph, 1u);
            if (TERMS == 2) {
                const __half* pl = Wlo + (size_t)(n0 + r) * FF + k0 + seg * 8;
                cp16(sWl + soff, pl, 1u);
            }
        }
        CP_COMMIT();
    };

    load_chunk(0, 0);

    for (int c = 0; c < 4; c++) {
        if (c < 3) {
            load_chunk(c + 1, (c + 1) & 1);
            cp_wait<1>();
        } else {
            cp_wait<0>();
        }
        __syncthreads();

        uint32_t sA  = base + (uint32_t)(c & 1) * STAGE;
        uint32_t sWh = sA + 16384u;
        uint32_t sWl = sA + 32768u;

        #pragma unroll
        for (int kk = 0; kk < 4; kk++) {
            uint32_t bh[4][2], bl[4][2];
            #pragma unroll
            for (int fnp = 0; fnp < 2; fnp++) {
                uint32_t brow = (uint32_t)(wn * 32 + fnp * 16 + ((lane >> 4) << 3) + (lane & 7));
                uint32_t bseg = (uint32_t)(kk * 2 + ((lane >> 3) & 1));
                uint32_t tmp[4];
                ldmx4(tmp, sWh + swz(brow * 128 + bseg * 16));
                bh[fnp * 2][0] = tmp[0]; bh[fnp * 2][1] = tmp[1];
                bh[fnp * 2 + 1][0] = tmp[2]; bh[fnp * 2 + 1][1] = tmp[3];
                if (TERMS == 2) {
                    ldmx4(tmp, sWl + swz(brow * 128 + bseg * 16));
                    bl[fnp * 2][0] = tmp[0]; bl[fnp * 2][1] = tmp[1];
                    bl[fnp * 2 + 1][0] = tmp[2]; bl[fnp * 2 + 1][1] = tmp[3];
                }
            }
            #pragma unroll
            for (int fm = 0; fm < 4; fm++) {
                uint32_t arow = (uint32_t)(wm * 64 + fm * 16 + (lane & 15));
                uint32_t aseg = (uint32_t)(kk * 2 + (lane >> 4));
                uint32_t ah[4];
                ldmx4(ah, sA + swz(arow * 128 + aseg * 16));
                #pragma unroll
                for (int fn = 0; fn < 4; fn++) {
                    mma16816(acc[fm][fn], ah, bh[fn]);
                    if (TERMS == 2) mma16816(acc[fm][fn], ah, bl[fn]);
                }
            }
        }
        __syncthreads();
    }

    // ---- epilogue ----
    #pragma unroll
    for (int fm = 0; fm < 4; fm++) {
        int m = row0 + wm * 64 + fm * 16 + (lane >> 2);
        #pragma unroll
        for (int fn = 0; fn < 4; fn++) {
            if (TERMS == 2) {
                int col = (n0 - 256) + wn * 32 + fn * 8 + (lane & 3) * 2;
                float2 b2 = *(const float2*)(bias + col);
                if (m < M) {
                    float2 v = make_float2(acc[fm][fn][0] + b2.x, acc[fm][fn][1] + b2.y);
                    *(float2*)(Y + (size_t)m * FF + col) = v;
                }
                if (m + 8 < M) {
                    float2 v = make_float2(acc[fm][fn][2] + b2.x, acc[fm][fn][3] + b2.y);
                    *(float2*)(Y + (size_t)(m + 8) * FF + col) = v;
                }
            } else {
                int col = n0 + wn * 32 + fn * 8 + (lane & 3) * 2;
                if (m < M)
                    *(__half2*)(H + (size_t)m * FF + col) =
                        __floats2half2_rn(acc[fm][fn][0], acc[fm][fn][1]);
                if (m + 8 < M)
                    *(__half2*)(H + (size_t)(m + 8) * FF + col) =
                        __floats2half2_rn(acc[fm][fn][2], acc[fm][fn][3]);
            }
        }
    }
}

// ---------------- aggregation ----------------
// xnext[n,f] = relu(y[n,f] + sum_j cw[j]*h[csrc[j],f]), h fp16
// MODE 0: write fp16 into g_xf16 (next GEMM A). MODE 1: write fp32 out.
template <int MODE>
__global__ __launch_bounds__(128)
void agg_kernel(float* __restrict__ xnext) {
    int n = blockIdx.x * 2 + (threadIdx.x >> 6);
    if (n >= NN) return;
    int f = (threadIdx.x & 63) * 4;

    float4 acc = *(const float4*)(g_y + (size_t)n * FF + f);
    int j = g_rowptr[n], end = g_rowptr[n + 1];

    auto fetch = [&](int s) -> float4 {
        uint2 raw = *(const uint2*)(g_h + (size_t)s * FF + f);
        float2 ab = __half22float2(*(__half2*)&raw.x);
        float2 cd = __half22float2(*(__half2*)&raw.y);
        return make_float4(ab.x, ab.y, cd.x, cd.y);
    };

    for (; j + 4 <= end; j += 4) {
        int s0 = g_csrc[j], s1 = g_csrc[j + 1], s2 = g_csrc[j + 2], s3 = g_csrc[j + 3];
        float w0 = g_cw[j], w1 = g_cw[j + 1], w2 = g_cw[j + 2], w3 = g_cw[j + 3];
        float4 h0 = fetch(s0), h1 = fetch(s1), h2 = fetch(s2), h3 = fetch(s3);
        acc.x = fmaf(w0, h0.x, fmaf(w1, h1.x, fmaf(w2, h2.x, fmaf(w3, h3.x, acc.x))));
        acc.y = fmaf(w0, h0.y, fmaf(w1, h1.y, fmaf(w2, h2.y, fmaf(w3, h3.y, acc.y))));
        acc.z = fmaf(w0, h0.z, fmaf(w1, h1.z, fmaf(w2, h2.z, fmaf(w3, h3.z, acc.z))));
        acc.w = fmaf(w0, h0.w, fmaf(w1, h1.w, fmaf(w2, h2.w, fmaf(w3, h3.w, acc.w))));
    }
    for (; j < end; j++) {
        float w0 = g_cw[j];
        float4 h0 = fetch(g_csrc[j]);
        acc.x = fmaf(w0, h0.x, acc.x);
        acc.y = fmaf(w0, h0.y, acc.y);
        acc.z = fmaf(w0, h0.z, acc.z);
        acc.w = fmaf(w0, h0.w, acc.w);
    }
    acc.x = fmaxf(acc.x, 0.f);
    acc.y = fmaxf(acc.y, 0.f);
    acc.z = fmaxf(acc.z, 0.f);
    acc.w = fmaxf(acc.w, 0.f);

    if (MODE == 1) {
        *(float4*)(xnext + (size_t)n * FF + f) = acc;
    } else {
        uint2 p;
        *(__half2*)&p.x = __floats2half2_rn(acc.x, acc.y);
        *(__half2*)&p.y = __floats2half2_rn(acc.z, acc.w);
        *(uint2*)(g_xf16 + (size_t)n * FF + f) = p;
    }
}

// ---------------- launch ----------------
extern "C" void kernel_launch(void* const* d_in, const int* in_sizes, int n_in,
                              void* d_out, int out_size) {
    const float* x    = (const float*)d_in[0];
    const int*   ei   = (const int*)d_in[1];
    const float* w    = (const float*)d_in[2];
    const float* Wi   = (const float*)d_in[3];
    const float* Wr   = (const float*)d_in[4];
    const float* bias = (const float*)d_in[5];
    float* out = (float*)d_out;

    const int* src = ei;
    const int* dst = ei + EE;

    void *p_deg, *p_cnt, *p_h, *p_y, *p_xf16, *p_Whi, *p_Wlo;
    cudaGetSymbolAddress(&p_deg,  g_deg);
    cudaGetSymbolAddress(&p_cnt,  g_cnt);
    cudaGetSymbolAddress(&p_h,    g_h);
    cudaGetSymbolAddress(&p_y,    g_y);
    cudaGetSymbolAddress(&p_xf16, g_xf16);
    cudaGetSymbolAddress(&p_Whi,  g_Whi);
    cudaGetSymbolAddress(&p_Wlo,  g_Wlo);

    static cudaStream_t s2 = nullptr;
    static cudaEvent_t evFork = nullptr, evW = nullptr, evJoin = nullptr;
    static cudaEvent_t evX = nullptr, evY[LL], evAgg[LL];
    if (!s2) {
        cudaStreamCreateWithFlags(&s2, cudaStreamNonBlocking);
        cudaEventCreateWithFlags(&evFork, cudaEventDisableTiming);
        cudaEventCreateWithFlags(&evW, cudaEventDisableTiming);
        cudaEventCreateWithFlags(&evJoin, cudaEventDisableTiming);
        cudaEventCreateWithFlags(&evX, cudaEventDisableTiming);
        for (int l = 0; l < LL; l++) {
            cudaEventCreateWithFlags(&evY[l], cudaEventDisableTiming);
            cudaEventCreateWithFlags(&evAgg[l], cudaEventDisableTiming);
        }
        cudaFuncSetAttribute(hmma_gemm_kernel<1>,
                             cudaFuncAttributeMaxDynamicSharedMemorySize, GSM1);
        cudaFuncSetAttribute(hmma_gemm_kernel<2>,
                             cudaFuncAttributeMaxDynamicSharedMemorySize, GSM2);
    }

    // ---- fork: weight convert + CSR setup chain on side stream ----
    cudaEventRecord(evFork, 0);
    cudaStreamWaitEvent(s2, evFork, 0);
    convert_w_kernel<<<(3 * 512 * 256 + 255) / 256, 256, 0, s2>>>(Wi, Wr);
    cudaEventRecord(evW, s2);
    cudaMemsetAsync(p_deg, 0, NN * sizeof(float), s2);
    cudaMemsetAsync(p_cnt, 0, NN * sizeof(int), s2);
    hist_kernel<<<(EE + 255) / 256, 256, 0, s2>>>(src, dst, w);
    dinv_kernel<<<(NN + 255) / 256, 256, 0, s2>>>();
    scan_local<<<NB, 256, 0, s2>>>();
    scan_blocks<<<1, 256, 0, s2>>>();
    scan_finish<<<NB, 256, 0, s2>>>();
    fill_kernel<<<(EE + 255) / 256, 256, 0, s2>>>(src, dst, w);
    cudaEventRecord(evJoin, s2);

    // ---- main: layer-0 activations -> fp16 ----
    convert_x_kernel<<<(NN * FF / 4 + 255) / 256, 256>>>(x);
    cudaStreamWaitEvent(0, evW, 0);
    cudaEventRecord(evX, 0);

    dim3 ggrid(2, (NN + 127) / 128);
    const __half* Whi = (const __half*)p_Whi;
    const __half* Wlo = (const __half*)p_Wlo;

    for (int l = 0; l < LL; l++) {
        const float* bl = bias + (size_t)l * FF;
        const __half* Whl = Whi + (size_t)l * 512 * 256;
        const __half* Wll = Wlo + (size_t)l * 512 * 256;

        // Y-GEMM on side stream s2 (independent of H-GEMM; both read xf16)
        cudaStreamWaitEvent(s2, (l == 0) ? evX : evAgg[l - 1], 0);
        hmma_gemm_kernel<2><<<ggrid, 256, GSM2, s2>>>((const __half*)p_xf16, Whl, Wll,
                                                      bl, nullptr, (float*)p_y, NN, 2);
        cudaEventRecord(evY[l], s2);

        // H-GEMM on main stream — tails of the two launches backfill each other
        hmma_gemm_kernel<1><<<ggrid, 256, GSM1>>>((const __half*)p_xf16, Whl, nullptr,
                                                  nullptr, (__half*)p_h, nullptr, NN, 0);

        if (l == 0) cudaStreamWaitEvent(0, evJoin, 0);   // CSR ready before first agg
        cudaStreamWaitEvent(0, evY[l], 0);               // y ready
        if (l < LL - 1)
            agg_kernel<0><<<(NN + 1) / 2, 128>>>(nullptr);
        else
            agg_kernel<1><<<(NN + 1) / 2, 128>>>(out);
        if (l < LL - 1) cudaEventRecord(evAgg[l], 0);    // xf16 ready for next layer
    }
}

// round 14
// speedup vs baseline: 1.1357x; 1.1357x over previous
#include <cuda_runtime.h>
#include <cuda_fp16.h>
#include <cstdint>
#include <cstddef>

#define NN 50000
#define EE 800000
#define FF 256
#define LL 3
#define NB 196   // ceil(NN/256)

// ---------------- scratch (device globals) ----------------
__device__ float g_deg[NN];
__device__ float g_dinv[NN];
__device__ int   g_cnt[NN];
__device__ int   g_rowptr[NN + 1];
__device__ int   g_cursor[NN];
__device__ int   g_bsum[NB];
__device__ int   g_boff[NB];
__device__ int   g_csrc[EE];
__device__ float g_cw[EE];
__device__ __half g_h[(size_t)NN * FF];      // h = x@Wi in fp16 (agg gather operand)
__device__ float  g_y[(size_t)NN * FF];      // y = x@Wr + b in fp32
__device__ __half g_xf16[(size_t)NN * FF];   // activations in fp16 (GEMM A operand)
// fused transposed weights, fp16 (1-term): [layer][512][256]
// rows 0-255 = Wi^T, rows 256-511 = Wr^T
__device__ __half g_Whi[3 * 512 * 256];

// ---------------- helpers ----------------
__device__ __forceinline__ uint32_t smem_u32(const void* p) {
    uint32_t a;
    asm("{ .reg .u64 t; cvta.to.shared.u64 t, %1; cvt.u32.u64 %0, t; }"
        : "=r"(a) : "l"(p));
    return a;
}
// 64B-row swizzle
__device__ __forceinline__ uint32_t swz64(uint32_t off) { return off ^ ((off >> 3) & 0x30); }

__device__ __forceinline__ void ldmx4(uint32_t* r, uint32_t addr) {
    asm volatile("ldmatrix.sync.aligned.m8n8.x4.shared.b16 {%0,%1,%2,%3}, [%4];"
                 : "=r"(r[0]), "=r"(r[1]), "=r"(r[2]), "=r"(r[3]) : "r"(addr));
}
__device__ __forceinline__ void mma16816(float* c, const uint32_t* a, const uint32_t* b) {
    asm volatile(
        "mma.sync.aligned.m16n8k16.row.col.f32.f16.f16.f32 "
        "{%0,%1,%2,%3}, {%4,%5,%6,%7}, {%8,%9}, {%0,%1,%2,%3};"
        : "+f"(c[0]), "+f"(c[1]), "+f"(c[2]), "+f"(c[3])
        : "r"(a[0]), "r"(a[1]), "r"(a[2]), "r"(a[3]), "r"(b[0]), "r"(b[1]));
}
__device__ __forceinline__ void cp16(uint32_t dst, const void* src, uint32_t valid) {
    asm volatile("cp.async.cg.shared.global [%0], [%1], 16, %2;"
                 :: "r"(dst), "l"(src), "r"(valid ? 16u : 0u));
}
#define CP_COMMIT() asm volatile("cp.async.commit_group;" ::: "memory")
template <int N> __device__ __forceinline__ void cp_wait() {
    asm volatile("cp.async.wait_group %0;" :: "n"(N) : "memory");
}

// ---------------- setup kernels ----------------
__global__ void hist_kernel(const int* __restrict__ src, const int* __restrict__ dst,
                            const float* __restrict__ w) {
    int e = blockIdx.x * blockDim.x + threadIdx.x;
    if (e >= EE) return;
    int d = dst[e];
    atomicAdd(&g_deg[d], w[e]);
    atomicAdd(&g_cnt[d], 1);
}

__global__ void dinv_kernel() {
    int n = blockIdx.x * blockDim.x + threadIdx.x;
    if (n >= NN) return;
    float d = g_deg[n];
    g_dinv[n] = (d > 0.f) ? rsqrtf(d) : 0.f;
}

__global__ void scan_local() {
    __shared__ int sh[256];
    int b = blockIdx.x, tid = threadIdx.x, i = b * 256 + tid;
    int v = (i < NN) ? g_cnt[i] : 0;
    sh[tid] = v;
    __syncthreads();
    #pragma unroll
    for (int off = 1; off < 256; off <<= 1) {
        int t2 = (tid >= off) ? sh[tid - off] : 0;
        __syncthreads();
        sh[tid] += t2;
        __syncthreads();
    }
    if (i < NN) g_rowptr[i] = sh[tid];
    if (tid == 255) g_bsum[b] = sh[255];
}
__global__ void scan_blocks() {
    __shared__ int sh[256];
    int tid = threadIdx.x;
    int v = (tid < NB) ? g_bsum[tid] : 0;
    sh[tid] = v;
    __syncthreads();
    #pragma unroll
    for (int off = 1; off < 256; off <<= 1) {
        int t2 = (tid >= off) ? sh[tid - off] : 0;
        __syncthreads();
        sh[tid] += t2;
        __syncthreads();
    }
    if (tid < NB) g_boff[tid] = sh[tid] - v;
    if (tid == NB - 1) g_rowptr[NN] = sh[tid];
}
__global__ void scan_finish() {
    int i = blockIdx.x * 256 + threadIdx.x;
    if (i >= NN) return;
    int excl = g_rowptr[i] - g_cnt[i] + g_boff[blockIdx.x];
    g_rowptr[i] = excl;
    g_cursor[i] = excl;
}

__global__ void fill_kernel(const int* __restrict__ src, const int* __restrict__ dst,
                            const float* __restrict__ w) {
    int e = blockIdx.x * blockDim.x + threadIdx.x;
    if (e >= EE) return;
    int s = src[e];
    int d = dst[e];
    int pos = atomicAdd(&g_cursor[d], 1);
    g_csrc[pos] = s;
    g_cw[pos] = g_dinv[s] * w[e] * g_dinv[d];
}

// weights: transpose into fused [l][512][256], fp16
__global__ void convert_w_kernel(const float* __restrict__ Wi, const float* __restrict__ Wr) {
    int idx = blockIdx.x * blockDim.x + threadIdx.x;
    if (idx >= 3 * 512 * 256) return;
    int l = idx >> 17;
    int n = (idx >> 8) & 511;
    int k = idx & 255;
    const float* W = (n < 256) ? Wi : Wr;
    int nn = n & 255;
    float v = W[(size_t)l * FF * FF + (size_t)k * FF + nn];
    g_Whi[idx] = __float2half(v);
}

// layer-0 activations -> fp16
__global__ void convert_x_kernel(const float* __restrict__ x) {
    int idx = blockIdx.x * blockDim.x + threadIdx.x;   // over NN*FF/4
    if (idx >= NN * FF / 4) return;
    float4 v = *(const float4*)(x + idx * 4);
    uint2 p;
    *(__half2*)&p.x = __floats2half2_rn(v.x, v.y);
    *(__half2*)&p.y = __floats2half2_rn(v.z, v.w);
    *(uint2*)(g_xf16 + (size_t)idx * 4) = p;
}

// ---------------- HMMA fp16 GEMM (cp.async 2-stage, 1-term) ----------------
// OUTF32=false: H(fp16) = A @ Wi^T; W rows [0,256).  grid.x=2, ntBase=0
// OUTF32=true:  Y(fp32)+bias = A @ Wr^T; W rows [256,512). grid.x=2, ntBase=2
// CTA tile 128x128, K-chunk 32, SMEM rows 64B swz64. Stage = 8KB A + 8KB W.
#define GSM 32768
template <bool OUTF32>
__global__ __launch_bounds__(256, 2)
void hmma_gemm_kernel(const __half* __restrict__ A,
                      const __half* __restrict__ Whi,
                      const float* __restrict__ bias,
                      __half* __restrict__ H, float* __restrict__ Y,
                      int M, int ntBase) {
    constexpr uint32_t STAGE = 16384u;
    extern __shared__ __align__(1024) uint8_t dsm[];
    const uint32_t base = smem_u32(dsm);

    int t = threadIdx.x;
    int lane = t & 31, wid = t >> 5;
    int wm = wid >> 2;        // 0..1
    int wn = wid & 3;         // 0..3
    int row0 = blockIdx.y * 128;
    int nt   = ntBase + blockIdx.x;
    int n0   = nt * 128;      // fused W row base

    float acc[4][4][4];
    #pragma unroll
    for (int i = 0; i < 4; i++)
        #pragma unroll
        for (int j = 0; j < 4; j++)
            #pragma unroll
            for (int q = 0; q < 4; q++) acc[i][j][q] = 0.f;

    auto load_chunk = [&](int c, int stage) {
        int k0 = c * 32;
        uint32_t sA = base + (uint32_t)stage * STAGE;
        uint32_t sW = sA + 8192u;
        #pragma unroll
        for (int u = 0; u < 2; u++) {
            int idx = t + u * 256;            // 0..511 = 128 rows x 4 segs
            int r = idx >> 2;
            int seg = idx & 3;
            uint32_t soff = swz64((uint32_t)r * 64 + (uint32_t)seg * 16);
            int gm = row0 + r;
            const __half* pa = A + (size_t)(gm < M ? gm : 0) * FF + k0 + seg * 8;
            cp16(sA + soff, pa, (uint32_t)(gm < M));
            const __half* ph = Whi + (size_t)(n0 + r) * FF + k0 + seg * 8;
            cp16(sW + soff, ph, 1u);
        }
        CP_COMMIT();
    };

    load_chunk(0, 0);

    for (int c = 0; c < 8; c++) {
        if (c < 7) {
            load_chunk(c + 1, (c + 1) & 1);
            cp_wait<1>();
        } else {
            cp_wait<0>();
        }
        __syncthreads();

        uint32_t sA = base + (uint32_t)(c & 1) * STAGE;
        uint32_t sW = sA + 8192u;

        #pragma unroll
        for (int kk = 0; kk < 2; kk++) {
            uint32_t bh[4][2];
            #pragma unroll
            for (int fnp = 0; fnp < 2; fnp++) {
                uint32_t brow = (uint32_t)(wn * 32 + fnp * 16 + ((lane >> 4) << 3) + (lane & 7));
                uint32_t bseg = (uint32_t)(kk * 2 + ((lane >> 3) & 1));
                uint32_t tmp[4];
                ldmx4(tmp, sW + swz64(brow * 64 + bseg * 16));
                bh[fnp * 2][0] = tmp[0]; bh[fnp * 2][1] = tmp[1];
                bh[fnp * 2 + 1][0] = tmp[2]; bh[fnp * 2 + 1][1] = tmp[3];
            }
            #pragma unroll
            for (int fm = 0; fm < 4; fm++) {
                uint32_t arow = (uint32_t)(wm * 64 + fm * 16 + (lane & 15));
                uint32_t aseg = (uint32_t)(kk * 2 + (lane >> 4));
                uint32_t ah[4];
                ldmx4(ah, sA + swz64(arow * 64 + aseg * 16));
                #pragma unroll
                for (int fn = 0; fn < 4; fn++) {
                    mma16816(acc[fm][fn], ah, bh[fn]);
                }
            }
        }
        __syncthreads();
    }

    // ---- epilogue ----
    #pragma unroll
    for (int fm = 0; fm < 4; fm++) {
        int m = row0 + wm * 64 + fm * 16 + (lane >> 2);
        #pragma unroll
        for (int fn = 0; fn < 4; fn++) {
            if (OUTF32) {
                int col = (n0 - 256) + wn * 32 + fn * 8 + (lane & 3) * 2;
                float2 b2 = *(const float2*)(bias + col);
                if (m < M) {
                    float2 v = make_float2(acc[fm][fn][0] + b2.x, acc[fm][fn][1] + b2.y);
                    *(float2*)(Y + (size_t)m * FF + col) = v;
                }
                if (m + 8 < M) {
                    float2 v = make_float2(acc[fm][fn][2] + b2.x, acc[fm][fn][3] + b2.y);
                    *(float2*)(Y + (size_t)(m + 8) * FF + col) = v;
                }
            } else {
                int col = n0 + wn * 32 + fn * 8 + (lane & 3) * 2;
                if (m < M)
                    *(__half2*)(H + (size_t)m * FF + col) =
                        __floats2half2_rn(acc[fm][fn][0], acc[fm][fn][1]);
                if (m + 8 < M)
                    *(__half2*)(H + (size_t)(m + 8) * FF + col) =
                        __floats2half2_rn(acc[fm][fn][2], acc[fm][fn][3]);
            }
        }
    }
}

// ---------------- aggregation ----------------
// xnext[n,f] = relu(y[n,f] + sum_j cw[j]*h[csrc[j],f]), h fp16
// MODE 0: write fp16 into g_xf16 (next GEMM A). MODE 1: write fp32 out.
template <int MODE>
__global__ __launch_bounds__(128)
void agg_kernel(float* __restrict__ xnext) {
    int n = blockIdx.x * 2 + (threadIdx.x >> 6);
    if (n >= NN) return;
    int f = (threadIdx.x & 63) * 4;

    float4 acc = *(const float4*)(g_y + (size_t)n * FF + f);
    int j = g_rowptr[n], end = g_rowptr[n + 1];

    auto fetch = [&](int s) -> float4 {
        uint2 raw = *(const uint2*)(g_h + (size_t)s * FF + f);
        float2 ab = __half22float2(*(__half2*)&raw.x);
        float2 cd = __half22float2(*(__half2*)&raw.y);
        return make_float4(ab.x, ab.y, cd.x, cd.y);
    };

    for (; j + 4 <= end; j += 4) {
        int s0 = g_csrc[j], s1 = g_csrc[j + 1], s2 = g_csrc[j + 2], s3 = g_csrc[j + 3];
        float w0 = g_cw[j], w1 = g_cw[j + 1], w2 = g_cw[j + 2], w3 = g_cw[j + 3];
        float4 h0 = fetch(s0), h1 = fetch(s1), h2 = fetch(s2), h3 = fetch(s3);
        acc.x = fmaf(w0, h0.x, fmaf(w1, h1.x, fmaf(w2, h2.x, fmaf(w3, h3.x, acc.x))));
        acc.y = fmaf(w0, h0.y, fmaf(w1, h1.y, fmaf(w2, h2.y, fmaf(w3, h3.y, acc.y))));
        acc.z = fmaf(w0, h0.z, fmaf(w1, h1.z, fmaf(w2, h2.z, fmaf(w3, h3.z, acc.z))));
        acc.w = fmaf(w0, h0.w, fmaf(w1, h1.w, fmaf(w2, h2.w, fmaf(w3, h3.w, acc.w))));
    }
    for (; j < end; j++) {
        float w0 = g_cw[j];
        float4 h0 = fetch(g_csrc[j]);
        acc.x = fmaf(w0, h0.x, acc.x);
        acc.y = fmaf(w0, h0.y, acc.y);
        acc.z = fmaf(w0, h0.z, acc.z);
        acc.w = fmaf(w0, h0.w, acc.w);
    }
    acc.x = fmaxf(acc.x, 0.f);
    acc.y = fmaxf(acc.y, 0.f);
    acc.z = fmaxf(acc.z, 0.f);
    acc.w = fmaxf(acc.w, 0.f);

    if (MODE == 1) {
        *(float4*)(xnext + (size_t)n * FF + f) = acc;
    } else {
        uint2 p;
        *(__half2*)&p.x = __floats2half2_rn(acc.x, acc.y);
        *(__half2*)&p.y = __floats2half2_rn(acc.z, acc.w);
        *(uint2*)(g_xf16 + (size_t)n * FF + f) = p;
    }
}

// ---------------- launch ----------------
extern "C" void kernel_launch(void* const* d_in, const int* in_sizes, int n_in,
                              void* d_out, int out_size) {
    const float* x    = (const float*)d_in[0];
    const int*   ei   = (const int*)d_in[1];
    const float* w    = (const float*)d_in[2];
    const float* Wi   = (const float*)d_in[3];
    const float* Wr   = (const float*)d_in[4];
    const float* bias = (const float*)d_in[5];
    float* out = (float*)d_out;

    const int* src = ei;
    const int* dst = ei + EE;

    void *p_deg, *p_cnt, *p_h, *p_y, *p_xf16, *p_Whi;
    cudaGetSymbolAddress(&p_deg,  g_deg);
    cudaGetSymbolAddress(&p_cnt,  g_cnt);
    cudaGetSymbolAddress(&p_h,    g_h);
    cudaGetSymbolAddress(&p_y,    g_y);
    cudaGetSymbolAddress(&p_xf16, g_xf16);
    cudaGetSymbolAddress(&p_Whi,  g_Whi);

    static cudaStream_t s2 = nullptr;
    static cudaEvent_t evFork = nullptr, evW = nullptr, evJoin = nullptr;
    static cudaEvent_t evX = nullptr, evY[LL], evAgg[LL];
    if (!s2) {
        cudaStreamCreateWithFlags(&s2, cudaStreamNonBlocking);
        cudaEventCreateWithFlags(&evFork, cudaEventDisableTiming);
        cudaEventCreateWithFlags(&evW, cudaEventDisableTiming);
        cudaEventCreateWithFlags(&evJoin, cudaEventDisableTiming);
        cudaEventCreateWithFlags(&evX, cudaEventDisableTiming);
        for (int l = 0; l < LL; l++) {
            cudaEventCreateWithFlags(&evY[l], cudaEventDisableTiming);
            cudaEventCreateWithFlags(&evAgg[l], cudaEventDisableTiming);
        }
        cudaFuncSetAttribute(hmma_gemm_kernel<false>,
                             cudaFuncAttributeMaxDynamicSharedMemorySize, GSM);
        cudaFuncSetAttribute(hmma_gemm_kernel<true>,
                             cudaFuncAttributeMaxDynamicSharedMemorySize, GSM);
    }

    // ---- fork: weight convert + CSR setup chain on side stream ----
    cudaEventRecord(evFork, 0);
    cudaStreamWaitEvent(s2, evFork, 0);
    convert_w_kernel<<<(3 * 512 * 256 + 255) / 256, 256, 0, s2>>>(Wi, Wr);
    cudaEventRecord(evW, s2);
    cudaMemsetAsync(p_deg, 0, NN * sizeof(float), s2);
    cudaMemsetAsync(p_cnt, 0, NN * sizeof(int), s2);
    hist_kernel<<<(EE + 255) / 256, 256, 0, s2>>>(src, dst, w);
    dinv_kernel<<<(NN + 255) / 256, 256, 0, s2>>>();
    scan_local<<<NB, 256, 0, s2>>>();
    scan_blocks<<<1, 256, 0, s2>>>();
    scan_finish<<<NB, 256, 0, s2>>>();
    fill_kernel<<<(EE + 255) / 256, 256, 0, s2>>>(src, dst, w);
    cudaEventRecord(evJoin, s2);

    // ---- main: layer-0 activations -> fp16 ----
    convert_x_kernel<<<(NN * FF / 4 + 255) / 256, 256>>>(x);
    cudaStreamWaitEvent(0, evW, 0);
    cudaEventRecord(evX, 0);

    dim3 ggrid(2, (NN + 127) / 128);
    const __half* Whi = (const __half*)p_Whi;

    for (int l = 0; l < LL; l++) {
        const float* bl = bias + (size_t)l * FF;
        const __half* Whl = Whi + (size_t)l * 512 * 256;

        // Y-GEMM on side stream s2 (independent of H-GEMM; both read xf16)
        cudaStreamWaitEvent(s2, (l == 0) ? evX : evAgg[l - 1], 0);
        hmma_gemm_kernel<true><<<ggrid, 256, GSM, s2>>>((const __half*)p_xf16, Whl,
                                                        bl, nullptr, (float*)p_y, NN, 2);
        cudaEventRecord(evY[l], s2);

        // H-GEMM on main stream — tails of the two launches backfill each other
        hmma_gemm_kernel<false><<<ggrid, 256, GSM>>>((const __half*)p_xf16, Whl,
                                                     nullptr, (__half*)p_h, nullptr, NN, 0);

        if (l == 0) cudaStreamWaitEvent(0, evJoin, 0);   // CSR ready before first agg
        cudaStreamWaitEvent(0, evY[l], 0);               // y ready
        if (l < LL - 1)
            agg_kernel<0><<<(NN + 1) / 2, 128>>>(nullptr);
        else
            agg_kernel<1><<<(NN + 1) / 2, 128>>>(out);
        if (l < LL - 1) cudaEventRecord(evAgg[l], 0);    // xf16 ready for next layer
    }
}

// round 15
// speedup vs baseline: 1.1766x; 1.0360x over previous
#include <cuda_runtime.h>
#include <cuda_fp16.h>
#include <cstdint>
#include <cstddef>

#define NN 50000
#define EE 800000
#define FF 256
#define LL 3
#define NB 196   // ceil(NN/256)

// ---------------- scratch (device globals) ----------------
__device__ float g_deg[NN];
__device__ float g_dinv[NN];
__device__ int   g_cnt[NN];
__device__ int   g_rowptr[NN + 1];
__device__ int   g_cursor[NN];
__device__ int   g_bsum[NB];
__device__ int   g_boff[NB];
__device__ int   g_csrc[EE];
__device__ float g_cw[EE];
__device__ __half g_h[(size_t)NN * FF];      // h = x@Wi in fp16 (agg gather operand)
__device__ __half g_yf16[(size_t)NN * FF];   // y = x@Wr + b in fp16
__device__ __half g_xf16[(size_t)NN * FF];   // activations in fp16 (GEMM A operand)
// fused transposed weights, fp16 (1-term): [layer][512][256]
// rows 0-255 = Wi^T, rows 256-511 = Wr^T
__device__ __half g_Whi[3 * 512 * 256];

// ---------------- helpers ----------------
__device__ __forceinline__ uint32_t smem_u32(const void* p) {
    uint32_t a;
    asm("{ .reg .u64 t; cvta.to.shared.u64 t, %1; cvt.u32.u64 %0, t; }"
        : "=r"(a) : "l"(p));
    return a;
}
// 64B-row swizzle
__device__ __forceinline__ uint32_t swz64(uint32_t off) { return off ^ ((off >> 3) & 0x30); }

__device__ __forceinline__ void ldmx4(uint32_t* r, uint32_t addr) {
    asm volatile("ldmatrix.sync.aligned.m8n8.x4.shared.b16 {%0,%1,%2,%3}, [%4];"
                 : "=r"(r[0]), "=r"(r[1]), "=r"(r[2]), "=r"(r[3]) : "r"(addr));
}
__device__ __forceinline__ void mma16816(float* c, const uint32_t* a, const uint32_t* b) {
    asm volatile(
        "mma.sync.aligned.m16n8k16.row.col.f32.f16.f16.f32 "
        "{%0,%1,%2,%3}, {%4,%5,%6,%7}, {%8,%9}, {%0,%1,%2,%3};"
        : "+f"(c[0]), "+f"(c[1]), "+f"(c[2]), "+f"(c[3])
        : "r"(a[0]), "r"(a[1]), "r"(a[2]), "r"(a[3]), "r"(b[0]), "r"(b[1]));
}
__device__ __forceinline__ void cp16(uint32_t dst, const void* src, uint32_t valid) {
    asm volatile("cp.async.cg.shared.global [%0], [%1], 16, %2;"
                 :: "r"(dst), "l"(src), "r"(valid ? 16u : 0u));
}
#define CP_COMMIT() asm volatile("cp.async.commit_group;" ::: "memory")
template <int N> __device__ __forceinline__ void cp_wait() {
    asm volatile("cp.async.wait_group %0;" :: "n"(N) : "memory");
}

// ---------------- setup kernels ----------------
__global__ void hist_kernel(const int* __restrict__ src, const int* __restrict__ dst,
                            const float* __restrict__ w) {
    int e = blockIdx.x * blockDim.x + threadIdx.x;
    if (e >= EE) return;
    int d = dst[e];
    atomicAdd(&g_deg[d], w[e]);
    atomicAdd(&g_cnt[d], 1);
}

__global__ void dinv_kernel() {
    int n = blockIdx.x * blockDim.x + threadIdx.x;
    if (n >= NN) return;
    float d = g_deg[n];
    g_dinv[n] = (d > 0.f) ? rsqrtf(d) : 0.f;
}

__global__ void scan_local() {
    __shared__ int sh[256];
    int b = blockIdx.x, tid = threadIdx.x, i = b * 256 + tid;
    int v = (i < NN) ? g_cnt[i] : 0;
    sh[tid] = v;
    __syncthreads();
    #pragma unroll
    for (int off = 1; off < 256; off <<= 1) {
        int t2 = (tid >= off) ? sh[tid - off] : 0;
        __syncthreads();
        sh[tid] += t2;
        __syncthreads();
    }
    if (i < NN) g_rowptr[i] = sh[tid];
    if (tid == 255) g_bsum[b] = sh[255];
}
__global__ void scan_blocks() {
    __shared__ int sh[256];
    int tid = threadIdx.x;
    int v = (tid < NB) ? g_bsum[tid] : 0;
    sh[tid] = v;
    __syncthreads();
    #pragma unroll
    for (int off = 1; off < 256; off <<= 1) {
        int t2 = (tid >= off) ? sh[tid - off] : 0;
        __syncthreads();
        sh[tid] += t2;
        __syncthreads();
    }
    if (tid < NB) g_boff[tid] = sh[tid] - v;
    if (tid == NB - 1) g_rowptr[NN] = sh[tid];
}
__global__ void scan_finish() {
    int i = blockIdx.x * 256 + threadIdx.x;
    if (i >= NN) return;
    int excl = g_rowptr[i] - g_cnt[i] + g_boff[blockIdx.x];
    g_rowptr[i] = excl;
    g_cursor[i] = excl;
}

__global__ void fill_kernel(const int* __restrict__ src, const int* __restrict__ dst,
                            const float* __restrict__ w) {
    int e = blockIdx.x * blockDim.x + threadIdx.x;
    if (e >= EE) return;
    int s = src[e];
    int d = dst[e];
    int pos = atomicAdd(&g_cursor[d], 1);
    g_csrc[pos] = s;
    g_cw[pos] = g_dinv[s] * w[e] * g_dinv[d];
}

// weights: transpose into fused [l][512][256], fp16
__global__ void convert_w_kernel(const float* __restrict__ Wi, const float* __restrict__ Wr) {
    int idx = blockIdx.x * blockDim.x + threadIdx.x;
    if (idx >= 3 * 512 * 256) return;
    int l = idx >> 17;
    int n = (idx >> 8) & 511;
    int k = idx & 255;
    const float* W = (n < 256) ? Wi : Wr;
    int nn = n & 255;
    float v = W[(size_t)l * FF * FF + (size_t)k * FF + nn];
    g_Whi[idx] = __float2half(v);
}

// layer-0 activations -> fp16
__global__ void convert_x_kernel(const float* __restrict__ x) {
    int idx = blockIdx.x * blockDim.x + threadIdx.x;   // over NN*FF/4
    if (idx >= NN * FF / 4) return;
    float4 v = *(const float4*)(x + idx * 4);
    uint2 p;
    *(__half2*)&p.x = __floats2half2_rn(v.x, v.y);
    *(__half2*)&p.y = __floats2half2_rn(v.z, v.w);
    *(uint2*)(g_xf16 + (size_t)idx * 4) = p;
}

// ---------------- merged HMMA fp16 GEMM (cp.async 2-stage, 1-term) ----------------
// One launch, grid.x=4 (homogeneous mainloop, epilogue routes output):
//   nt 0,1: H(fp16)   = A @ Wi^T                 (W rows [0,256))
//   nt 2,3: Y(fp16)   = A @ Wr^T + bias          (W rows [256,512))
// CTA tile 128x128, K-chunk 32, SMEM rows 64B swz64. Stage = 8KB A + 8KB W.
#define GSM 32768
__global__ __launch_bounds__(256, 2)
void hmma_gemm_kernel(const __half* __restrict__ A,
                      const __half* __restrict__ Whi,
                      const float* __restrict__ bias,
                      __half* __restrict__ H, __half* __restrict__ Y, int M) {
    constexpr uint32_t STAGE = 16384u;
    extern __shared__ __align__(1024) uint8_t dsm[];
    const uint32_t base = smem_u32(dsm);

    int t = threadIdx.x;
    int lane = t & 31, wid = t >> 5;
    int wm = wid >> 2;        // 0..1
    int wn = wid & 3;         // 0..3
    int row0 = blockIdx.y * 128;
    int nt   = blockIdx.x;    // 0..3
    int n0   = nt * 128;      // fused W row base

    float acc[4][4][4];
    #pragma unroll
    for (int i = 0; i < 4; i++)
        #pragma unroll
        for (int j = 0; j < 4; j++)
            #pragma unroll
            for (int q = 0; q < 4; q++) acc[i][j][q] = 0.f;

    auto load_chunk = [&](int c, int stage) {
        int k0 = c * 32;
        uint32_t sA = base + (uint32_t)stage * STAGE;
        uint32_t sW = sA + 8192u;
        #pragma unroll
        for (int u = 0; u < 2; u++) {
            int idx = t + u * 256;            // 0..511 = 128 rows x 4 segs
            int r = idx >> 2;
            int seg = idx & 3;
            uint32_t soff = swz64((uint32_t)r * 64 + (uint32_t)seg * 16);
            int gm = row0 + r;
            const __half* pa = A + (size_t)(gm < M ? gm : 0) * FF + k0 + seg * 8;
            cp16(sA + soff, pa, (uint32_t)(gm < M));
            const __half* ph = Whi + (size_t)(n0 + r) * FF + k0 + seg * 8;
            cp16(sW + soff, ph, 1u);
        }
        CP_COMMIT();
    };

    load_chunk(0, 0);

    for (int c = 0; c < 8; c++) {
        if (c < 7) {
            load_chunk(c + 1, (c + 1) & 1);
            cp_wait<1>();
        } else {
            cp_wait<0>();
        }
        __syncthreads();

        uint32_t sA = base + (uint32_t)(c & 1) * STAGE;
        uint32_t sW = sA + 8192u;

        #pragma unroll
        for (int kk = 0; kk < 2; kk++) {
            uint32_t bh[4][2];
            #pragma unroll
            for (int fnp = 0; fnp < 2; fnp++) {
                uint32_t brow = (uint32_t)(wn * 32 + fnp * 16 + ((lane >> 4) << 3) + (lane & 7));
                uint32_t bseg = (uint32_t)(kk * 2 + ((lane >> 3) & 1));
                uint32_t tmp[4];
                ldmx4(tmp, sW + swz64(brow * 64 + bseg * 16));
                bh[fnp * 2][0] = tmp[0]; bh[fnp * 2][1] = tmp[1];
                bh[fnp * 2 + 1][0] = tmp[2]; bh[fnp * 2 + 1][1] = tmp[3];
            }
            #pragma unroll
            for (int fm = 0; fm < 4; fm++) {
                uint32_t arow = (uint32_t)(wm * 64 + fm * 16 + (lane & 15));
                uint32_t aseg = (uint32_t)(kk * 2 + (lane >> 4));
                uint32_t ah[4];
                ldmx4(ah, sA + swz64(arow * 64 + aseg * 16));
                #pragma unroll
                for (int fn = 0; fn < 4; fn++) {
                    mma16816(acc[fm][fn], ah, bh[fn]);
                }
            }
        }
        __syncthreads();
    }

    // ---- epilogue: fp16 out; Y half adds bias ----
    const bool isY = (nt >= 2);
    __half* C = isY ? Y : H;
    int cb = n0 & 255;   // column base within [0,256)

    #pragma unroll
    for (int fm = 0; fm < 4; fm++) {
        int m = row0 + wm * 64 + fm * 16 + (lane >> 2);
        #pragma unroll
        for (int fn = 0; fn < 4; fn++) {
            int col = cb + wn * 32 + fn * 8 + (lane & 3) * 2;
            float bx = 0.f, by = 0.f;
            if (isY) {
                float2 b2 = *(const float2*)(bias + col);
                bx = b2.x; by = b2.y;
            }
            if (m < M)
                *(__half2*)(C + (size_t)m * FF + col) =
                    __floats2half2_rn(acc[fm][fn][0] + bx, acc[fm][fn][1] + by);
            if (m + 8 < M)
                *(__half2*)(C + (size_t)(m + 8) * FF + col) =
                    __floats2half2_rn(acc[fm][fn][2] + bx, acc[fm][fn][3] + by);
        }
    }
}

// ---------------- aggregation ----------------
// xnext[n,f] = relu(y[n,f] + sum_j cw[j]*h[csrc[j],f]), h & y fp16
// MODE 0: write fp16 into g_xf16 (next GEMM A). MODE 1: write fp32 out.
template <int MODE>
__global__ __launch_bounds__(128)
void agg_kernel(float* __restrict__ xnext) {
    int n = blockIdx.x * 2 + (threadIdx.x >> 6);
    if (n >= NN) return;
    int f = (threadIdx.x & 63) * 4;

    auto fetch16 = [&](const __half* buf, int s) -> float4 {
        uint2 raw = *(const uint2*)(buf + (size_t)s * FF + f);
        float2 ab = __half22float2(*(__half2*)&raw.x);
        float2 cd = __half22float2(*(__half2*)&raw.y);
        return make_float4(ab.x, ab.y, cd.x, cd.y);
    };

    float4 acc = fetch16(g_yf16, n);
    int j = g_rowptr[n], end = g_rowptr[n + 1];

    for (; j + 4 <= end; j += 4) {
        int s0 = g_csrc[j], s1 = g_csrc[j + 1], s2 = g_csrc[j + 2], s3 = g_csrc[j + 3];
        float w0 = g_cw[j], w1 = g_cw[j + 1], w2 = g_cw[j + 2], w3 = g_cw[j + 3];
        float4 h0 = fetch16(g_h, s0), h1 = fetch16(g_h, s1);
        float4 h2 = fetch16(g_h, s2), h3 = fetch16(g_h, s3);
        acc.x = fmaf(w0, h0.x, fmaf(w1, h1.x, fmaf(w2, h2.x, fmaf(w3, h3.x, acc.x))));
        acc.y = fmaf(w0, h0.y, fmaf(w1, h1.y, fmaf(w2, h2.y, fmaf(w3, h3.y, acc.y))));
        acc.z = fmaf(w0, h0.z, fmaf(w1, h1.z, fmaf(w2, h2.z, fmaf(w3, h3.z, acc.z))));
        acc.w = fmaf(w0, h0.w, fmaf(w1, h1.w, fmaf(w2, h2.w, fmaf(w3, h3.w, acc.w))));
    }
    for (; j < end; j++) {
        float w0 = g_cw[j];
        float4 h0 = fetch16(g_h, g_csrc[j]);
        acc.x = fmaf(w0, h0.x, acc.x);
        acc.y = fmaf(w0, h0.y, acc.y);
        acc.z = fmaf(w0, h0.z, acc.z);
        acc.w = fmaf(w0, h0.w, acc.w);
    }
    acc.x = fmaxf(acc.x, 0.f);
    acc.y = fmaxf(acc.y, 0.f);
    acc.z = fmaxf(acc.z, 0.f);
    acc.w = fmaxf(acc.w, 0.f);

    if (MODE == 1) {
        *(float4*)(xnext + (size_t)n * FF + f) = acc;
    } else {
        uint2 p;
        *(__half2*)&p.x = __floats2half2_rn(acc.x, acc.y);
        *(__half2*)&p.y = __floats2half2_rn(acc.z, acc.w);
        *(uint2*)(g_xf16 + (size_t)n * FF + f) = p;
    }
}

// ---------------- launch ----------------
extern "C" void kernel_launch(void* const* d_in, const int* in_sizes, int n_in,
                              void* d_out, int out_size) {
    const float* x    = (const float*)d_in[0];
    const int*   ei   = (const int*)d_in[1];
    const float* w    = (const float*)d_in[2];
    const float* Wi   = (const float*)d_in[3];
    const float* Wr   = (const float*)d_in[4];
    const float* bias = (const float*)d_in[5];
    float* out = (float*)d_out;

    const int* src = ei;
    const int* dst = ei + EE;

    void *p_deg, *p_cnt, *p_h, *p_yf16, *p_xf16, *p_Whi;
    cudaGetSymbolAddress(&p_deg,  g_deg);
    cudaGetSymbolAddress(&p_cnt,  g_cnt);
    cudaGetSymbolAddress(&p_h,    g_h);
    cudaGetSymbolAddress(&p_yf16, g_yf16);
    cudaGetSymbolAddress(&p_xf16, g_xf16);
    cudaGetSymbolAddress(&p_Whi,  g_Whi);

    static cudaStream_t s2 = nullptr;
    static cudaEvent_t evFork = nullptr, evW = nullptr, evJoin = nullptr;
    if (!s2) {
        cudaStreamCreateWithFlags(&s2, cudaStreamNonBlocking);
        cudaEventCreateWithFlags(&evFork, cudaEventDisableTiming);
        cudaEventCreateWithFlags(&evW, cudaEventDisableTiming);
        cudaEventCreateWithFlags(&evJoin, cudaEventDisableTiming);
        cudaFuncSetAttribute(hmma_gemm_kernel,
                             cudaFuncAttributeMaxDynamicSharedMemorySize, GSM);
    }

    // ---- fork: weight convert + CSR setup chain on side stream ----
    cudaEventRecord(evFork, 0);
    cudaStreamWaitEvent(s2, evFork, 0);
    convert_w_kernel<<<(3 * 512 * 256 + 255) / 256, 256, 0, s2>>>(Wi, Wr);
    cudaEventRecord(evW, s2);
    cudaMemsetAsync(p_deg, 0, NN * sizeof(float), s2);
    cudaMemsetAsync(p_cnt, 0, NN * sizeof(int), s2);
    hist_kernel<<<(EE + 255) / 256, 256, 0, s2>>>(src, dst, w);
    dinv_kernel<<<(NN + 255) / 256, 256, 0, s2>>>();
    scan_local<<<NB, 256, 0, s2>>>();
    scan_blocks<<<1, 256, 0, s2>>>();
    scan_finish<<<NB, 256, 0, s2>>>();
    fill_kernel<<<(EE + 255) / 256, 256, 0, s2>>>(src, dst, w);
    cudaEventRecord(evJoin, s2);

    // ---- main: layer-0 activations -> fp16 ----
    convert_x_kernel<<<(NN * FF / 4 + 255) / 256, 256>>>(x);
    cudaStreamWaitEvent(0, evW, 0);

    dim3 ggrid(4, (NN + 127) / 128);
    const __half* Whi = (const __half*)p_Whi;

    for (int l = 0; l < LL; l++) {
        const float* bl = bias + (size_t)l * FF;

        hmma_gemm_kernel<<<ggrid, 256, GSM>>>((const __half*)p_xf16,
                                              Whi + (size_t)l * 512 * 256,
                                              bl, (__half*)p_h, (__half*)p_yf16, NN);
        if (l == 0) cudaStreamWaitEvent(0, evJoin, 0);   // CSR ready before first agg
        if (l < LL - 1)
            agg_kernel<0><<<(NN + 1) / 2, 128>>>(nullptr);
        else
            agg_kernel<1><<<(NN + 1) / 2, 128>>>(out);
    }
}

// round 16
// speedup vs baseline: 1.1926x; 1.0136x over previous
#include <cuda_runtime.h>
#include <cuda_fp16.h>
#include <cstdint>
#include <cstddef>

#define NN 50000
#define EE 800000
#define FF 256
#define LL 3
#define NB 196   // ceil(NN/256)

// ---------------- scratch (device globals) ----------------
__device__ float g_deg[NN];
__device__ float g_dinv[NN];
__device__ int   g_cnt[NN];
__device__ int   g_rowptr[NN + 1];
__device__ int   g_cursor[NN];
__device__ int   g_bsum[NB];
__device__ int   g_boff[NB];
__device__ int   g_csrc[EE];
__device__ float g_cw[EE];
__device__ __half g_h[(size_t)NN * FF];      // h = x@Wi in fp16 (agg gather operand)
__device__ __half g_yf16[(size_t)NN * FF];   // y = x@Wr + b in fp16
__device__ __half g_xf16[(size_t)NN * FF];   // activations in fp16 (GEMM A operand)
// fused transposed weights, fp16 (1-term): [layer][512][256]
// rows 0-255 = Wi^T, rows 256-511 = Wr^T
__device__ __half g_Whi[3 * 512 * 256];

// ---------------- helpers ----------------
__device__ __forceinline__ uint32_t smem_u32(const void* p) {
    uint32_t a;
    asm("{ .reg .u64 t; cvta.to.shared.u64 t, %1; cvt.u32.u64 %0, t; }"
        : "=r"(a) : "l"(p));
    return a;
}
// 64B-row swizzle
__device__ __forceinline__ uint32_t swz64(uint32_t off) { return off ^ ((off >> 3) & 0x30); }

__device__ __forceinline__ void ldmx4(uint32_t* r, uint32_t addr) {
    asm volatile("ldmatrix.sync.aligned.m8n8.x4.shared.b16 {%0,%1,%2,%3}, [%4];"
                 : "=r"(r[0]), "=r"(r[1]), "=r"(r[2]), "=r"(r[3]) : "r"(addr));
}
__device__ __forceinline__ void mma16816(float* c, const uint32_t* a, const uint32_t* b) {
    asm volatile(
        "mma.sync.aligned.m16n8k16.row.col.f32.f16.f16.f32 "
        "{%0,%1,%2,%3}, {%4,%5,%6,%7}, {%8,%9}, {%0,%1,%2,%3};"
        : "+f"(c[0]), "+f"(c[1]), "+f"(c[2]), "+f"(c[3])
        : "r"(a[0]), "r"(a[1]), "r"(a[2]), "r"(a[3]), "r"(b[0]), "r"(b[1]));
}
__device__ __forceinline__ void cp16(uint32_t dst, const void* src, uint32_t valid) {
    asm volatile("cp.async.cg.shared.global [%0], [%1], 16, %2;"
                 :: "r"(dst), "l"(src), "r"(valid ? 16u : 0u));
}
#define CP_COMMIT() asm volatile("cp.async.commit_group;" ::: "memory")
template <int N> __device__ __forceinline__ void cp_wait() {
    asm volatile("cp.async.wait_group %0;" :: "n"(N) : "memory");
}

// ---------------- setup kernels ----------------
__global__ void hist_kernel(const int* __restrict__ src, const int* __restrict__ dst,
                            const float* __restrict__ w) {
    int e = blockIdx.x * blockDim.x + threadIdx.x;
    if (e >= EE) return;
    int d = dst[e];
    atomicAdd(&g_deg[d], w[e]);
    atomicAdd(&g_cnt[d], 1);
}

__global__ void dinv_kernel() {
    int n = blockIdx.x * blockDim.x + threadIdx.x;
    if (n >= NN) return;
    float d = g_deg[n];
    g_dinv[n] = (d > 0.f) ? rsqrtf(d) : 0.f;
}

__global__ void scan_local() {
    __shared__ int sh[256];
    int b = blockIdx.x, tid = threadIdx.x, i = b * 256 + tid;
    int v = (i < NN) ? g_cnt[i] : 0;
    sh[tid] = v;
    __syncthreads();
    #pragma unroll
    for (int off = 1; off < 256; off <<= 1) {
        int t2 = (tid >= off) ? sh[tid - off] : 0;
        __syncthreads();
        sh[tid] += t2;
        __syncthreads();
    }
    if (i < NN) g_rowptr[i] = sh[tid];
    if (tid == 255) g_bsum[b] = sh[255];
}
__global__ void scan_blocks() {
    __shared__ int sh[256];
    int tid = threadIdx.x;
    int v = (tid < NB) ? g_bsum[tid] : 0;
    sh[tid] = v;
    __syncthreads();
    #pragma unroll
    for (int off = 1; off < 256; off <<= 1) {
        int t2 = (tid >= off) ? sh[tid - off] : 0;
        __syncthreads();
        sh[tid] += t2;
        __syncthreads();
    }
    if (tid < NB) g_boff[tid] = sh[tid] - v;
    if (tid == NB - 1) g_rowptr[NN] = sh[tid];
}
__global__ void scan_finish() {
    int i = blockIdx.x * 256 + threadIdx.x;
    if (i >= NN) return;
    int excl = g_rowptr[i] - g_cnt[i] + g_boff[blockIdx.x];
    g_rowptr[i] = excl;
    g_cursor[i] = excl;
}

__global__ void fill_kernel(const int* __restrict__ src, const int* __restrict__ dst,
                            const float* __restrict__ w) {
    int e = blockIdx.x * blockDim.x + threadIdx.x;
    if (e >= EE) return;
    int s = src[e];
    int d = dst[e];
    int pos = atomicAdd(&g_cursor[d], 1);
    g_csrc[pos] = s;
    g_cw[pos] = g_dinv[s] * w[e] * g_dinv[d];
}

// weights: transpose into fused [l][512][256], fp16
__global__ void convert_w_kernel(const float* __restrict__ Wi, const float* __restrict__ Wr) {
    int idx = blockIdx.x * blockDim.x + threadIdx.x;
    if (idx >= 3 * 512 * 256) return;
    int l = idx >> 17;
    int n = (idx >> 8) & 511;
    int k = idx & 255;
    const float* W = (n < 256) ? Wi : Wr;
    int nn = n & 255;
    float v = W[(size_t)l * FF * FF + (size_t)k * FF + nn];
    g_Whi[idx] = __float2half(v);
}

// layer-0 activations -> fp16
__global__ void convert_x_kernel(const float* __restrict__ x) {
    int idx = blockIdx.x * blockDim.x + threadIdx.x;   // over NN*FF/4
    if (idx >= NN * FF / 4) return;
    float4 v = *(const float4*)(x + idx * 4);
    uint2 p;
    *(__half2*)&p.x = __floats2half2_rn(v.x, v.y);
    *(__half2*)&p.y = __floats2half2_rn(v.z, v.w);
    *(uint2*)(g_xf16 + (size_t)idx * 4) = p;
}

// ---------------- merged HMMA fp16 GEMM (cp.async 2-stage, 1-term) ----------------
// One launch, grid.x=4 (homogeneous mainloop, epilogue routes output):
//   nt 0,1: H(fp16)   = A @ Wi^T                 (W rows [0,256))
//   nt 2,3: Y(fp16)   = A @ Wr^T + bias          (W rows [256,512))
// CTA tile 128x128, K-chunk 32, SMEM rows 64B swz64. Stage = 8KB A + 8KB W.
#define GSM 32768
__global__ __launch_bounds__(256, 2)
void hmma_gemm_kernel(const __half* __restrict__ A,
                      const __half* __restrict__ Whi,
                      const float* __restrict__ bias,
                      __half* __restrict__ H, __half* __restrict__ Y, int M) {
    constexpr uint32_t STAGE = 16384u;
    extern __shared__ __align__(1024) uint8_t dsm[];
    const uint32_t base = smem_u32(dsm);

    int t = threadIdx.x;
    int lane = t & 31, wid = t >> 5;
    int wm = wid >> 2;        // 0..1
    int wn = wid & 3;         // 0..3
    int row0 = blockIdx.y * 128;
    int nt   = blockIdx.x;    // 0..3
    int n0   = nt * 128;      // fused W row base

    float acc[4][4][4];
    #pragma unroll
    for (int i = 0; i < 4; i++)
        #pragma unroll
        for (int j = 0; j < 4; j++)
            #pragma unroll
            for (int q = 0; q < 4; q++) acc[i][j][q] = 0.f;

    auto load_chunk = [&](int c, int stage) {
        int k0 = c * 32;
        uint32_t sA = base + (uint32_t)stage * STAGE;
        uint32_t sW = sA + 8192u;
        #pragma unroll
        for (int u = 0; u < 2; u++) {
            int idx = t + u * 256;            // 0..511 = 128 rows x 4 segs
            int r = idx >> 2;
            int seg = idx & 3;
            uint32_t soff = swz64((uint32_t)r * 64 + (uint32_t)seg * 16);
            int gm = row0 + r;
            const __half* pa = A + (size_t)(gm < M ? gm : 0) * FF + k0 + seg * 8;
            cp16(sA + soff, pa, (uint32_t)(gm < M));
            const __half* ph = Whi + (size_t)(n0 + r) * FF + k0 + seg * 8;
            cp16(sW + soff, ph, 1u);
        }
        CP_COMMIT();
    };

    load_chunk(0, 0);

    for (int c = 0; c < 8; c++) {
        if (c < 7) {
            load_chunk(c + 1, (c + 1) & 1);
            cp_wait<1>();
        } else {
            cp_wait<0>();
        }
        __syncthreads();

        uint32_t sA = base + (uint32_t)(c & 1) * STAGE;
        uint32_t sW = sA + 8192u;

        #pragma unroll
        for (int kk = 0; kk < 2; kk++) {
            uint32_t bh[4][2];
            #pragma unroll
            for (int fnp = 0; fnp < 2; fnp++) {
                uint32_t brow = (uint32_t)(wn * 32 + fnp * 16 + ((lane >> 4) << 3) + (lane & 7));
                uint32_t bseg = (uint32_t)(kk * 2 + ((lane >> 3) & 1));
                uint32_t tmp[4];
                ldmx4(tmp, sW + swz64(brow * 64 + bseg * 16));
                bh[fnp * 2][0] = tmp[0]; bh[fnp * 2][1] = tmp[1];
                bh[fnp * 2 + 1][0] = tmp[2]; bh[fnp * 2 + 1][1] = tmp[3];
            }
            #pragma unroll
            for (int fm = 0; fm < 4; fm++) {
                uint32_t arow = (uint32_t)(wm * 64 + fm * 16 + (lane & 15));
                uint32_t aseg = (uint32_t)(kk * 2 + (lane >> 4));
                uint32_t ah[4];
                ldmx4(ah, sA + swz64(arow * 64 + aseg * 16));
                #pragma unroll
                for (int fn = 0; fn < 4; fn++) {
                    mma16816(acc[fm][fn], ah, bh[fn]);
                }
            }
        }
        __syncthreads();
    }

    // ---- epilogue: fp16 out; Y half adds bias ----
    const bool isY = (nt >= 2);
    __half* C = isY ? Y : H;
    int cb = n0 & 255;   // column base within [0,256)

    #pragma unroll
    for (int fm = 0; fm < 4; fm++) {
        int m = row0 + wm * 64 + fm * 16 + (lane >> 2);
        #pragma unroll
        for (int fn = 0; fn < 4; fn++) {
            int col = cb + wn * 32 + fn * 8 + (lane & 3) * 2;
            float bx = 0.f, by = 0.f;
            if (isY) {
                float2 b2 = *(const float2*)(bias + col);
                bx = b2.x; by = b2.y;
            }
            if (m < M)
                *(__half2*)(C + (size_t)m * FF + col) =
                    __floats2half2_rn(acc[fm][fn][0] + bx, acc[fm][fn][1] + by);
            if (m + 8 < M)
                *(__half2*)(C + (size_t)(m + 8) * FF + col) =
                    __floats2half2_rn(acc[fm][fn][2] + bx, acc[fm][fn][3] + by);
        }
    }
}

// ---------------- aggregation ----------------
// xnext[n,f] = relu(y[n,f] + sum_j cw[j]*h[csrc[j],f]), h & y fp16
// MODE 0: write fp16 into g_xf16 (next GEMM A). MODE 1: write fp32 out.
template <int MODE>
__global__ __launch_bounds__(128)
void agg_kernel(float* __restrict__ xnext) {
    int n = blockIdx.x * 2 + (threadIdx.x >> 6);
    if (n >= NN) return;
    int f = (threadIdx.x & 63) * 4;

    auto fetch16 = [&](const __half* buf, int s) -> float4 {
        uint2 raw = *(const uint2*)(buf + (size_t)s * FF + f);
        float2 ab = __half22float2(*(__half2*)&raw.x);
        float2 cd = __half22float2(*(__half2*)&raw.y);
        return make_float4(ab.x, ab.y, cd.x, cd.y);
    };

    float4 acc = fetch16(g_yf16, n);
    int j = g_rowptr[n], end = g_rowptr[n + 1];

    for (; j + 4 <= end; j += 4) {
        int s0 = g_csrc[j], s1 = g_csrc[j + 1], s2 = g_csrc[j + 2], s3 = g_csrc[j + 3];
        float w0 = g_cw[j], w1 = g_cw[j + 1], w2 = g_cw[j + 2], w3 = g_cw[j + 3];
        float4 h0 = fetch16(g_h, s0), h1 = fetch16(g_h, s1);
        float4 h2 = fetch16(g_h, s2), h3 = fetch16(g_h, s3);
        acc.x = fmaf(w0, h0.x, fmaf(w1, h1.x, fmaf(w2, h2.x, fmaf(w3, h3.x, acc.x))));
        acc.y = fmaf(w0, h0.y, fmaf(w1, h1.y, fmaf(w2, h2.y, fmaf(w3, h3.y, acc.y))));
        acc.z = fmaf(w0, h0.z, fmaf(w1, h1.z, fmaf(w2, h2.z, fmaf(w3, h3.z, acc.z))));
        acc.w = fmaf(w0, h0.w, fmaf(w1, h1.w, fmaf(w2, h2.w, fmaf(w3, h3.w, acc.w))));
    }
    for (; j < end; j++) {
        float w0 = g_cw[j];
        float4 h0 = fetch16(g_h, g_csrc[j]);
        acc.x = fmaf(w0, h0.x, acc.x);
        acc.y = fmaf(w0, h0.y, acc.y);
        acc.z = fmaf(w0, h0.z, acc.z);
        acc.w = fmaf(w0, h0.w, acc.w);
    }
    acc.x = fmaxf(acc.x, 0.f);
    acc.y = fmaxf(acc.y, 0.f);
    acc.z = fmaxf(acc.z, 0.f);
    acc.w = fmaxf(acc.w, 0.f);

    if (MODE == 1) {
        *(float4*)(xnext + (size_t)n * FF + f) = acc;
    } else {
        uint2 p;
        *(__half2*)&p.x = __floats2half2_rn(acc.x, acc.y);
        *(__half2*)&p.y = __floats2half2_rn(acc.z, acc.w);
        *(uint2*)(g_xf16 + (size_t)n * FF + f) = p;
    }
}

// ---------------- launch ----------------
extern "C" void kernel_launch(void* const* d_in, const int* in_sizes, int n_in,
                              void* d_out, int out_size) {
    const float* x    = (const float*)d_in[0];
    const int*   ei   = (const int*)d_in[1];
    const float* w    = (const float*)d_in[2];
    const float* Wi   = (const float*)d_in[3];
    const float* Wr   = (const float*)d_in[4];
    const float* bias = (const float*)d_in[5];
    float* out = (float*)d_out;

    const int* src = ei;
    const int* dst = ei + EE;

    void *p_deg, *p_cnt, *p_h, *p_yf16, *p_xf16, *p_Whi;
    cudaGetSymbolAddress(&p_deg,  g_deg);
    cudaGetSymbolAddress(&p_cnt,  g_cnt);
    cudaGetSymbolAddress(&p_h,    g_h);
    cudaGetSymbolAddress(&p_yf16, g_yf16);
    cudaGetSymbolAddress(&p_xf16, g_xf16);
    cudaGetSymbolAddress(&p_Whi,  g_Whi);

    static cudaStream_t s2 = nullptr;
    static cudaEvent_t evFork = nullptr, evJoin = nullptr;
    if (!s2) {
        cudaStreamCreateWithFlags(&s2, cudaStreamNonBlocking);
        cudaEventCreateWithFlags(&evFork, cudaEventDisableTiming);
        cudaEventCreateWithFlags(&evJoin, cudaEventDisableTiming);
        cudaFuncSetAttribute(hmma_gemm_kernel,
                             cudaFuncAttributeMaxDynamicSharedMemorySize, GSM);
    }

    // ---- fork: pure CSR setup chain on side stream (no convert_w) ----
    cudaEventRecord(evFork, 0);
    cudaStreamWaitEvent(s2, evFork, 0);
    cudaMemsetAsync(p_deg, 0, NN * sizeof(float), s2);
    cudaMemsetAsync(p_cnt, 0, NN * sizeof(int), s2);
    hist_kernel<<<(EE + 255) / 256, 256, 0, s2>>>(src, dst, w);
    dinv_kernel<<<(NN + 255) / 256, 256, 0, s2>>>();
    scan_local<<<NB, 256, 0, s2>>>();
    scan_blocks<<<1, 256, 0, s2>>>();
    scan_finish<<<NB, 256, 0, s2>>>();
    fill_kernel<<<(EE + 255) / 256, 256, 0, s2>>>(src, dst, w);
    cudaEventRecord(evJoin, s2);

    // ---- main: weight convert + layer-0 activation convert + layers ----
    convert_w_kernel<<<(3 * 512 * 256 + 255) / 256, 256>>>(Wi, Wr);
    convert_x_kernel<<<(NN * FF / 4 + 255) / 256, 256>>>(x);

    dim3 ggrid(4, (NN + 127) / 128);
    const __half* Whi = (const __half*)p_Whi;

    for (int l = 0; l < LL; l++) {
        const float* bl = bias + (size_t)l * FF;

        hmma_gemm_kernel<<<ggrid, 256, GSM>>>((const __half*)p_xf16,
                                              Whi + (size_t)l * 512 * 256,
                                              bl, (__half*)p_h, (__half*)p_yf16, NN);
        if (l == 0) cudaStreamWaitEvent(0, evJoin, 0);   // CSR ready before first agg
        if (l < LL - 1)
            agg_kernel<0><<<(NN + 1) / 2, 128>>>(nullptr);
        else
            agg_kernel<1><<<(NN + 1) / 2, 128>>>(out);
    }
}